// round 2
// baseline (speedup 1.0000x reference)
#include <cuda_runtime.h>
#include <cuda_bf16.h>
#include <cstdint>

// Problem constants (fixed by dataset: B=4, S=2048, D=1024, O=1024, C=8)
#define T_TOK 8192
#define DIM_D 1024
#define DIM_O 1024
#define N_CAT 8

#define TM 128
#define TN 128
#define TK 16
#define MAX_TILES (T_TOK / TM + N_CAT)   // 72 upper bound on grouped-GEMM tiles

// ---------------- scratch (device globals; no allocation allowed) ----------
__device__ int g_counts[N_CAT];
__device__ int g_cursor[N_CAT];
__device__ int g_offsets[N_CAT];
__device__ int g_perm[T_TOK];
__device__ int g_tile_cat[MAX_TILES];
__device__ int g_tile_row[MAX_TILES];
__device__ int g_tile_rows[MAX_TILES];
__device__ int g_n_tiles;

// ---------------- setup kernels --------------------------------------------
__global__ void k_zero() {
    int t = threadIdx.x;
    if (t < N_CAT) { g_counts[t] = 0; g_cursor[t] = 0; }
}

__global__ void k_hist(const int* __restrict__ cid) {
    int t = blockIdx.x * blockDim.x + threadIdx.x;
    if (t < T_TOK) atomicAdd(&g_counts[cid[t] & (N_CAT - 1)], 1);
}

__global__ void k_scan_tiles() {
    // single thread: exclusive scan + tile descriptor build (trivial work)
    int off = 0;
    for (int c = 0; c < N_CAT; c++) {
        g_offsets[c] = off;
        off += g_counts[c];
    }
    int nt = 0;
    for (int c = 0; c < N_CAT; c++) {
        int cnt = g_counts[c];
        for (int r = 0; r < cnt; r += TM) {
            g_tile_cat[nt]  = c;
            g_tile_row[nt]  = g_offsets[c] + r;
            g_tile_rows[nt] = (cnt - r < TM) ? (cnt - r) : TM;
            nt++;
        }
    }
    g_n_tiles = nt;
}

__global__ void k_perm(const int* __restrict__ cid) {
    int t = blockIdx.x * blockDim.x + threadIdx.x;
    if (t < T_TOK) {
        int c = cid[t] & (N_CAT - 1);
        int pos = g_offsets[c] + atomicAdd(&g_cursor[c], 1);
        g_perm[pos] = t;
    }
}

// ---------------- grouped GEMM ----------------------------------------------
// Each CTA: one (token-tile, output-tile). A rows gathered via g_perm,
// output rows scattered back via the same permutation. Bias fused in epilogue.
__global__ __launch_bounds__(256, 2)
void k_gemm(const float* __restrict__ x,
            const float* __restrict__ weight,
            const float* __restrict__ bias,
            float* __restrict__ out) {
    const int tile = blockIdx.x;
    if (tile >= g_n_tiles) return;

    const int cat       = g_tile_cat[tile] & (N_CAT - 1);
    const int row_start = g_tile_row[tile];
    const int rows      = g_tile_rows[tile];
    const int n0        = blockIdx.y * TN;

    __shared__ float As[TK][TM];
    __shared__ float Bs[TK][TN];
    __shared__ int   toks[TM];

    const int tid = threadIdx.x;
    const int tx = tid & 15;       // 0..15 -> 8 output cols each
    const int ty = tid >> 4;       // 0..15 -> 8 token rows each

    if (tid < TM) toks[tid] = (tid < rows) ? g_perm[row_start + tid] : -1;
    __syncthreads();

    const float* __restrict__ W = weight + (size_t)cat * DIM_D * DIM_O + n0;

    float acc[8][8];
#pragma unroll
    for (int i = 0; i < 8; i++)
#pragma unroll
        for (int j = 0; j < 8; j++) acc[i][j] = 0.f;

    for (int k0 = 0; k0 < DIM_D; k0 += TK) {
        // ---- load A tile (gathered rows): 128 rows x 16 k = 512 float4
#pragma unroll
        for (int r = 0; r < 2; r++) {
            int idx = tid + r * 256;
            int m   = idx >> 2;           // token row within tile
            int seg = idx & 3;            // which float4 of the 16-wide slab
            int tok = toks[m];
            float4 v = make_float4(0.f, 0.f, 0.f, 0.f);
            if (tok >= 0)
                v = *reinterpret_cast<const float4*>(x + (size_t)tok * DIM_D + k0 + seg * 4);
            As[seg * 4 + 0][m] = v.x;
            As[seg * 4 + 1][m] = v.y;
            As[seg * 4 + 2][m] = v.z;
            As[seg * 4 + 3][m] = v.w;
        }
        // ---- load B tile: 16 k x 128 n = 512 float4 (fully coalesced)
#pragma unroll
        for (int r = 0; r < 2; r++) {
            int idx = tid + r * 256;
            int k   = idx >> 5;           // 0..15
            int c4  = idx & 31;           // float4 column
            float4 v = *reinterpret_cast<const float4*>(W + (size_t)(k0 + k) * DIM_O + c4 * 4);
            *reinterpret_cast<float4*>(&Bs[k][c4 * 4]) = v;
        }
        __syncthreads();

#pragma unroll
        for (int k = 0; k < TK; k++) {
            float a[8], b[8];
            *reinterpret_cast<float4*>(&a[0]) = *reinterpret_cast<const float4*>(&As[k][ty * 8]);
            *reinterpret_cast<float4*>(&a[4]) = *reinterpret_cast<const float4*>(&As[k][ty * 8 + 4]);
            *reinterpret_cast<float4*>(&b[0]) = *reinterpret_cast<const float4*>(&Bs[k][tx * 8]);
            *reinterpret_cast<float4*>(&b[4]) = *reinterpret_cast<const float4*>(&Bs[k][tx * 8 + 4]);
#pragma unroll
            for (int i = 0; i < 8; i++)
#pragma unroll
                for (int j = 0; j < 8; j++)
                    acc[i][j] += a[i] * b[j];
        }
        __syncthreads();
    }

    // ---- epilogue: add bias, scatter rows back to token order
    float bfrag[8];
#pragma unroll
    for (int j = 0; j < 8; j++)
        bfrag[j] = bias[cat * DIM_O + n0 + tx * 8 + j];

#pragma unroll
    for (int i = 0; i < 8; i++) {
        int m   = ty * 8 + i;
        int tok = toks[m];
        if (tok < 0) continue;
        float* o = out + (size_t)tok * DIM_O + n0 + tx * 8;
        float4 v0, v1;
        v0.x = acc[i][0] + bfrag[0];
        v0.y = acc[i][1] + bfrag[1];
        v0.z = acc[i][2] + bfrag[2];
        v0.w = acc[i][3] + bfrag[3];
        v1.x = acc[i][4] + bfrag[4];
        v1.y = acc[i][5] + bfrag[5];
        v1.z = acc[i][6] + bfrag[6];
        v1.w = acc[i][7] + bfrag[7];
        *reinterpret_cast<float4*>(o)     = v0;
        *reinterpret_cast<float4*>(o + 4) = v1;
    }
}

// ---------------- launch ----------------------------------------------------
extern "C" void kernel_launch(void* const* d_in, const int* in_sizes, int n_in,
                              void* d_out, int out_size) {
    const float* x    = (const float*)d_in[0];   // [T, D] fp32
    const int*   cid  = (const int*)d_in[1];     // [T] int32 (JAX x64-disabled downcast)
    const float* wgt  = (const float*)d_in[2];   // [C, D, O] fp32
    const float* bias = (const float*)d_in[3];   // [C, O] fp32
    float*       out  = (float*)d_out;           // [T, O] fp32

    (void)in_sizes; (void)n_in; (void)out_size;

    k_zero<<<1, 32>>>();
    k_hist<<<T_TOK / 256, 256>>>(cid);
    k_scan_tiles<<<1, 1>>>();
    k_perm<<<T_TOK / 256, 256>>>(cid);

    dim3 grid(MAX_TILES, DIM_O / TN);   // 72 x 8; CTAs past g_n_tiles exit early
    k_gemm<<<grid, 256>>>(x, wgt, bias, out);
}

// round 4
// speedup vs baseline: 2.1834x; 2.1834x over previous
#include <cuda_runtime.h>
#include <cuda_bf16.h>
#include <cstdint>

// Problem constants (fixed by dataset: B=4, S=2048, D=1024, O=1024, C=8)
#define T_TOK 8192
#define DIM_D 1024
#define DIM_O 1024
#define N_CAT 8

#define TM 128
#define TN 128
#define BK 64                        // K per smem stage (64 bf16 = 128B rows)
#define NCHUNK (DIM_D / BK)          // 16
#define MAX_TILES (T_TOK / TM + N_CAT)

// ---------------- device scratch (no allocation allowed) --------------------
__device__ int g_counts[N_CAT];
__device__ int g_cursor[N_CAT];
__device__ int g_offsets[N_CAT];
__device__ int g_perm[T_TOK];
__device__ int g_tile_cat[MAX_TILES];
__device__ int g_tile_row[MAX_TILES];
__device__ int g_tile_rows[MAX_TILES];
__device__ int g_n_tiles;

// bf16-split operands. A padded by TM rows: padding rows never written ->
// stay zero (module-load zero init) -> safe for partial tiles.
__device__ __nv_bfloat16 g_Ahi[(T_TOK + TM) * DIM_D];
__device__ __nv_bfloat16 g_Alo[(T_TOK + TM) * DIM_D];
__device__ __nv_bfloat16 g_Whi[N_CAT * DIM_O * DIM_D];   // transposed: [c][o][d]
__device__ __nv_bfloat16 g_Wlo[N_CAT * DIM_O * DIM_D];

// ---------------- PTX helpers (baseline features only: sm_80/75) ------------
__device__ __forceinline__ uint32_t smem_u32(const void* p) {
    uint32_t a;
    asm("{ .reg .u64 t; cvta.to.shared.u64 t, %1; cvt.u32.u64 %0, t; }" : "=r"(a) : "l"(p));
    return a;
}

#define CP_ASYNC16(dst, src) \
    asm volatile("cp.async.cg.shared.global [%0], [%1], 16;" :: "r"(dst), "l"(src) : "memory")
#define CP_COMMIT() asm volatile("cp.async.commit_group;" ::: "memory")
#define CP_WAIT0()  asm volatile("cp.async.wait_group 0;" ::: "memory")
#define CP_WAIT1()  asm volatile("cp.async.wait_group 1;" ::: "memory")

#define LDSM4(r0, r1, r2, r3, addr)                                              \
    asm volatile("ldmatrix.sync.aligned.m8n8.x4.shared.b16 {%0,%1,%2,%3}, [%4];" \
                 : "=r"(r0), "=r"(r1), "=r"(r2), "=r"(r3) : "r"(addr))

#define MMA_BF16(c, a, b)                                                        \
    asm volatile("mma.sync.aligned.m16n8k16.row.col.f32.bf16.bf16.f32 "          \
                 "{%0,%1,%2,%3}, {%4,%5,%6,%7}, {%8,%9}, {%0,%1,%2,%3};"         \
                 : "+f"((c)[0]), "+f"((c)[1]), "+f"((c)[2]), "+f"((c)[3])        \
                 : "r"((a)[0]), "r"((a)[1]), "r"((a)[2]), "r"((a)[3]),           \
                   "r"((b)[0]), "r"((b)[1]))

__device__ __forceinline__ uint32_t sw128(uint32_t off) {
    return off ^ ((off >> 3) & 0x70);
}

// ---------------- setup kernels ----------------------------------------------
__global__ void k_zero() {
    int t = threadIdx.x;
    if (t < N_CAT) { g_counts[t] = 0; g_cursor[t] = 0; }
}

__global__ void k_hist(const int* __restrict__ cid) {
    int t = blockIdx.x * blockDim.x + threadIdx.x;
    if (t < T_TOK) atomicAdd(&g_counts[cid[t] & (N_CAT - 1)], 1);
}

__global__ void k_scan_tiles() {
    int off = 0;
    for (int c = 0; c < N_CAT; c++) { g_offsets[c] = off; off += g_counts[c]; }
    int nt = 0;
    for (int c = 0; c < N_CAT; c++) {
        int cnt = g_counts[c];
        for (int r = 0; r < cnt; r += TM) {
            g_tile_cat[nt]  = c;
            g_tile_row[nt]  = g_offsets[c] + r;
            g_tile_rows[nt] = (cnt - r < TM) ? (cnt - r) : TM;
            nt++;
        }
    }
    g_n_tiles = nt;
}

__global__ void k_perm(const int* __restrict__ cid) {
    int t = blockIdx.x * blockDim.x + threadIdx.x;
    if (t < T_TOK) {
        int c = cid[t] & (N_CAT - 1);
        int pos = g_offsets[c] + atomicAdd(&g_cursor[c], 1);
        g_perm[pos] = t;
    }
}

// ---------------- conversion kernels ------------------------------------------
__global__ void k_conv_x(const float* __restrict__ x) {
    int p   = blockIdx.x;            // sorted position
    int tok = g_perm[p];
    int c   = threadIdx.x * 4;
    float4 v = *reinterpret_cast<const float4*>(x + (size_t)tok * DIM_D + c);

    __nv_bfloat16 h0 = __float2bfloat16(v.x), h1 = __float2bfloat16(v.y);
    __nv_bfloat16 h2 = __float2bfloat16(v.z), h3 = __float2bfloat16(v.w);
    __nv_bfloat16 l0 = __float2bfloat16(v.x - __bfloat162float(h0));
    __nv_bfloat16 l1 = __float2bfloat16(v.y - __bfloat162float(h1));
    __nv_bfloat16 l2 = __float2bfloat16(v.z - __bfloat162float(h2));
    __nv_bfloat16 l3 = __float2bfloat16(v.w - __bfloat162float(h3));

    uint2 uh, ul;
    uh.x = (uint32_t)*(unsigned short*)&h0 | ((uint32_t)*(unsigned short*)&h1 << 16);
    uh.y = (uint32_t)*(unsigned short*)&h2 | ((uint32_t)*(unsigned short*)&h3 << 16);
    ul.x = (uint32_t)*(unsigned short*)&l0 | ((uint32_t)*(unsigned short*)&l1 << 16);
    ul.y = (uint32_t)*(unsigned short*)&l2 | ((uint32_t)*(unsigned short*)&l3 << 16);

    *reinterpret_cast<uint2*>(&g_Ahi[(size_t)p * DIM_D + c]) = uh;
    *reinterpret_cast<uint2*>(&g_Alo[(size_t)p * DIM_D + c]) = ul;
}

__global__ void k_conv_w(const float* __restrict__ w) {
    __shared__ float t[32][33];
    int cat = blockIdx.z;
    int o0  = blockIdx.x * 32;
    int d0  = blockIdx.y * 32;
    int tx = threadIdx.x, ty = threadIdx.y;   // (32, 8)

    const float* src = w + ((size_t)cat << 20) + (size_t)d0 * DIM_O + o0;
#pragma unroll
    for (int i = 0; i < 4; i++)
        t[ty + 8 * i][tx] = src[(size_t)(ty + 8 * i) * DIM_O + tx];
    __syncthreads();

    size_t dst = ((size_t)cat << 20) + (size_t)o0 * DIM_D + d0;
#pragma unroll
    for (int i = 0; i < 4; i++) {
        float v = t[tx][ty + 8 * i];          // = w[d0+tx][o0+ty+8i]
        __nv_bfloat16 h = __float2bfloat16(v);
        __nv_bfloat16 l = __float2bfloat16(v - __bfloat162float(h));
        g_Whi[dst + (size_t)(ty + 8 * i) * DIM_D + tx] = h;
        g_Wlo[dst + (size_t)(ty + 8 * i) * DIM_D + tx] = l;
    }
}

// ---------------- mma.sync grouped GEMM -----------------------------------------
// smem: [0..512) toks, [512..1024) bias, [1024..) 2 stages of
// {Ahi 16K | Alo 16K | Bhi 16K | Blo 16K} = 64KB each.
#define SM_TOKS   0
#define SM_BIAS   512
#define SM_STAGE  1024
#define PART_BYTES  16384
#define STAGE_BYTES 65536
#define SMEM_TOTAL (SM_STAGE + 2 * STAGE_BYTES)

__global__ __launch_bounds__(256, 1)
void k_gemm_mma(const float* __restrict__ bias, float* __restrict__ out) {
    const int tile = blockIdx.x;
    if (tile >= g_n_tiles) return;

    const int cat       = g_tile_cat[tile] & (N_CAT - 1);
    const int row_start = g_tile_row[tile];
    const int rows      = g_tile_rows[tile];
    const int n0        = blockIdx.y * TN;

    extern __shared__ char smem[];
    const uint32_t sm = smem_u32(smem);
    const int tid  = threadIdx.x;
    const int wid  = tid >> 5;
    const int lane = tid & 31;
    const int wm   = wid >> 2;        // 0..1  -> m offset wm*64
    const int wn   = wid & 3;         // 0..3  -> n offset wn*32

    int*   toks   = reinterpret_cast<int*>(smem + SM_TOKS);
    float* bias_s = reinterpret_cast<float*>(smem + SM_BIAS);
    if (tid < TM) toks[tid] = (tid < rows) ? g_perm[row_start + tid] : -1;
    if (tid >= 128) bias_s[tid - 128] = bias[cat * DIM_O + n0 + tid - 128];

    // global row bases (bf16 rows = 2048B)
    const char* gbase[4];
    gbase[0] = reinterpret_cast<const char*>(g_Ahi) + (size_t)row_start * 2048;
    gbase[1] = reinterpret_cast<const char*>(g_Alo) + (size_t)row_start * 2048;
    gbase[2] = reinterpret_cast<const char*>(g_Whi) + (((size_t)cat << 10) + n0) * 2048;
    gbase[3] = reinterpret_cast<const char*>(g_Wlo) + (((size_t)cat << 10) + n0) * 2048;

    // ---- chunk loader: 4 arrays x 128 rows x 8 x 16B = 4096 cp.async, 16/thread
#define ISSUE_CHUNK(kc, buf)                                                       \
    _Pragma("unroll")                                                              \
    for (int t = 0; t < 16; t++) {                                                 \
        int idx = tid + t * 256;                                                   \
        int arr = idx >> 10;                                                       \
        int r   = (idx >> 3) & 127;                                                \
        int c   = idx & 7;                                                         \
        const char* src = gbase[arr] + (size_t)r * 2048 + (size_t)(kc) * 128 + c * 16; \
        uint32_t dst = sm + SM_STAGE + (buf) * STAGE_BYTES + arr * PART_BYTES      \
                     + sw128((uint32_t)(r * 128 + c * 16));                        \
        CP_ASYNC16(dst, src);                                                      \
    }                                                                              \
    CP_COMMIT();

    float acc[4][4][4];
#pragma unroll
    for (int i = 0; i < 4; i++)
#pragma unroll
        for (int j = 0; j < 4; j++)
#pragma unroll
            for (int k = 0; k < 4; k++) acc[i][j][k] = 0.f;

    ISSUE_CHUNK(0, 0);
    ISSUE_CHUNK(1, 1);

    // per-thread ldmatrix address components
    const int fr_row = lane & 15;     // fragment row within 16
    const int fr_kb  = lane >> 4;     // 0/1: which 16B k-block

    for (int it = 0; it < NCHUNK; it++) {
        if (it < NCHUNK - 1) { CP_WAIT1(); } else { CP_WAIT0(); }
        __syncthreads();

        const uint32_t st   = sm + SM_STAGE + (it & 1) * STAGE_BYTES;
        const uint32_t stAh = st;
        const uint32_t stAl = st + PART_BYTES;
        const uint32_t stBh = st + 2 * PART_BYTES;
        const uint32_t stBl = st + 3 * PART_BYTES;

#pragma unroll
        for (int ks = 0; ks < 4; ks++) {
            const uint32_t kcol = (uint32_t)((ks * 2 + fr_kb) * 16);

            uint32_t ah[4][4], al[4][4], bh[4][2], bl[4][2];
#pragma unroll
            for (int mi = 0; mi < 4; mi++) {
                uint32_t off = (uint32_t)((wm * 64 + mi * 16 + fr_row) * 128) + kcol;
                uint32_t a = sw128(off);
                LDSM4(ah[mi][0], ah[mi][1], ah[mi][2], ah[mi][3], stAh + a);
                LDSM4(al[mi][0], al[mi][1], al[mi][2], al[mi][3], stAl + a);
            }
#pragma unroll
            for (int pj = 0; pj < 2; pj++) {
                uint32_t off = (uint32_t)((wn * 32 + pj * 16 + fr_row) * 128) + kcol;
                uint32_t a = sw128(off);
                uint32_t r0, r1, r2, r3;
                LDSM4(r0, r1, r2, r3, stBh + a);
                bh[pj * 2][0]     = r0; bh[pj * 2][1]     = r2;
                bh[pj * 2 + 1][0] = r1; bh[pj * 2 + 1][1] = r3;
                LDSM4(r0, r1, r2, r3, stBl + a);
                bl[pj * 2][0]     = r0; bl[pj * 2][1]     = r2;
                bl[pj * 2 + 1][0] = r1; bl[pj * 2 + 1][1] = r3;
            }

#pragma unroll
            for (int mi = 0; mi < 4; mi++)
#pragma unroll
                for (int ni = 0; ni < 4; ni++) {
                    MMA_BF16(acc[mi][ni], ah[mi], bh[ni]);
                    MMA_BF16(acc[mi][ni], ah[mi], bl[ni]);
                    MMA_BF16(acc[mi][ni], al[mi], bh[ni]);
                }
        }

        __syncthreads();
        if (it + 2 < NCHUNK) { ISSUE_CHUNK(it + 2, it & 1); }
    }

    // ---- epilogue: bias + scatter (C fragment: rows t/4, t/4+8; cols 2(t%4)+{0,1})
#pragma unroll
    for (int mi = 0; mi < 4; mi++) {
        int m0   = wm * 64 + mi * 16 + (lane >> 2);
        int tok0 = toks[m0];
        int tok1 = toks[m0 + 8];
#pragma unroll
        for (int ni = 0; ni < 4; ni++) {
            int col = wn * 32 + ni * 8 + 2 * (lane & 3);
            float b0 = bias_s[col], b1 = bias_s[col + 1];
            if (tok0 >= 0) {
                float2 v = make_float2(acc[mi][ni][0] + b0, acc[mi][ni][1] + b1);
                *reinterpret_cast<float2*>(out + (size_t)tok0 * DIM_O + n0 + col) = v;
            }
            if (tok1 >= 0) {
                float2 v = make_float2(acc[mi][ni][2] + b0, acc[mi][ni][3] + b1);
                *reinterpret_cast<float2*>(out + (size_t)tok1 * DIM_O + n0 + col) = v;
            }
        }
    }
}

// ---------------- launch --------------------------------------------------------
extern "C" void kernel_launch(void* const* d_in, const int* in_sizes, int n_in,
                              void* d_out, int out_size) {
    const float* x    = (const float*)d_in[0];   // [T, D] fp32
    const int*   cid  = (const int*)d_in[1];     // [T] int32
    const float* wgt  = (const float*)d_in[2];   // [C, D, O] fp32
    const float* bias = (const float*)d_in[3];   // [C, O] fp32
    float*       out  = (float*)d_out;           // [T, O] fp32

    (void)in_sizes; (void)n_in; (void)out_size;

    cudaFuncSetAttribute(k_gemm_mma, cudaFuncAttributeMaxDynamicSharedMemorySize, SMEM_TOTAL);

    k_zero<<<1, 32>>>();
    k_hist<<<T_TOK / 256, 256>>>(cid);
    k_scan_tiles<<<1, 1>>>();
    k_perm<<<T_TOK / 256, 256>>>(cid);

    k_conv_x<<<T_TOK, 256>>>(x);
    k_conv_w<<<dim3(DIM_O / 32, DIM_D / 32, N_CAT), dim3(32, 8)>>>(wgt);

    dim3 grid(MAX_TILES, DIM_O / TN);   // 72 x 8; CTAs past g_n_tiles exit early
    k_gemm_mma<<<grid, 256, SMEM_TOTAL>>>(bias, out);
}